// round 15
// baseline (speedup 1.0000x reference)
#include <cuda_runtime.h>
#include <cuda_bf16.h>
#include <cstdint>

// ---------------------------------------------------------------------------
// GraphSAGE 2-layer backbone.
// R15: dense1 also emits h in bf16 (h16); gather2 consumes h16 -> layer-2
//      aggregation traffic halves (819MB -> 410MB). dense2 still reads fp32 h.
// ---------------------------------------------------------------------------

static constexpr int NN   = 100000;
static constexpr int EE   = 1600000;
static constexpr int F_IN = 64;
static constexpr int F_H  = 128;
static constexpr int SCAN_CHUNK = 512;

static constexpr int A_STRIDE = 144;
static constexpr int A_TILE   = 128 * A_STRIDE;
static constexpr int A_BUF    = 2 * A_TILE;
static constexpr int SMEM_BIAS_OFF = 2 * A_BUF;             // 73728
static constexpr int SMEM_TOTAL_D  = SMEM_BIAS_OFF + 512;   // 74240

// scratch
__device__ __align__(16) float    g_agg1 [(size_t)NN * F_IN];
__device__ __align__(16) float    g_h    [(size_t)NN * F_H];
__device__ __align__(16) uint32_t g_h16  [(size_t)NN * (F_H / 2)];  // bf16x2
__device__ __align__(16) float    g_agg2 [(size_t)NN * F_H];
__device__ __align__(16) float    g_dinv [NN];
__device__ __align__(16) int      g_degi [NN];
__device__ __align__(16) int      g_rowp [NN + 1];
__device__ __align__(16) int      g_curs [NN];
__device__ __align__(16) int      g_csr  [EE];
__device__ __align__(16) int      g_bsum [256];
__device__ __align__(16) int      g_boff [256];
__device__ __align__(16) uint4    g_bf1 [8  * 16 * 32];
__device__ __align__(16) uint4    g_bf2 [16 * 16 * 32];

// ---------------------------------------------------------------------------
__device__ __forceinline__ uint32_t smem_u32(const void* p) {
    uint32_t a;
    asm("{ .reg .u64 t; cvta.to.shared.u64 t, %1; cvt.u32.u64 %0, t; }"
        : "=r"(a) : "l"(p));
    return a;
}
__device__ __forceinline__ uint32_t bpack(float a, float b) {
    __nv_bfloat16 ha = __float2bfloat16_rn(a), hb = __float2bfloat16_rn(b);
    return (uint32_t)__bfloat16_as_ushort(ha)
         | ((uint32_t)__bfloat16_as_ushort(hb) << 16);
}
__device__ __forceinline__ float2 bunpack(uint32_t w) {
    __nv_bfloat16 lo = __ushort_as_bfloat16((unsigned short)(w & 0xFFFF));
    __nv_bfloat16 hi = __ushort_as_bfloat16((unsigned short)(w >> 16));
    return make_float2(__bfloat162float(lo), __bfloat162float(hi));
}

#define MMA_BF16(d, a, b0, b1)                                              \
    asm volatile("mma.sync.aligned.m16n8k16.row.col.f32.bf16.bf16.f32 "     \
        "{%0,%1,%2,%3}, {%4,%5,%6,%7}, {%8,%9}, {%0,%1,%2,%3};"             \
        : "+f"((d)[0]), "+f"((d)[1]), "+f"((d)[2]), "+f"((d)[3])            \
        : "r"((a)[0]), "r"((a)[1]), "r"((a)[2]), "r"((a)[3]),               \
          "r"(b0), "r"(b1))

#define LDMATRIX_X4(r, addr)                                                \
    asm volatile("ldmatrix.sync.aligned.m8n8.x4.shared.b16 "                \
        "{%0,%1,%2,%3}, [%4];"                                              \
        : "=r"((r)[0]), "=r"((r)[1]), "=r"((r)[2]), "=r"((r)[3])            \
        : "r"(addr))

// ---------------------------------------------------------------------------
// CSR build (unchanged)
__global__ void hist_kernel(const int* __restrict__ ei, int E, int nnodes,
                            int* __restrict__ degi) {
    const int half2 = E >> 1;
    int i = blockIdx.x * blockDim.x + threadIdx.x;
    if (i < half2) {
        int2 d2 = __ldg(reinterpret_cast<const int2*>(ei + E) + i);
        if ((unsigned)d2.x < (unsigned)nnodes) atomicAdd(&degi[d2.x], 1);
        if ((unsigned)d2.y < (unsigned)nnodes) atomicAdd(&degi[d2.y], 1);
    }
    if ((E & 1) && i == 0) {
        int d = __ldg(&ei[E + E - 1]);
        if ((unsigned)d < (unsigned)nnodes) atomicAdd(&degi[d], 1);
    }
}

__global__ void scan_partial_kernel(const int* __restrict__ degi,
                                    int* __restrict__ bsum, int n) {
    __shared__ int s[SCAN_CHUNK];
    int t = threadIdx.x;
    int i = blockIdx.x * SCAN_CHUNK + t;
    s[t] = (i < n) ? degi[i] : 0;
    __syncthreads();
    for (int off = SCAN_CHUNK / 2; off > 0; off >>= 1) {
        if (t < off) s[t] += s[t + off];
        __syncthreads();
    }
    if (t == 0) bsum[blockIdx.x] = s[0];
}

__global__ void scan_bsum_kernel(const int* __restrict__ bsum,
                                 int* __restrict__ boff,
                                 int* __restrict__ rowp, int nblk, int n) {
    __shared__ int s[256];
    int t = threadIdx.x;
    s[t] = (t < nblk) ? bsum[t] : 0;
    __syncthreads();
    for (int off = 1; off < 256; off <<= 1) {
        int v = (t >= off) ? s[t - off] : 0;
        __syncthreads();
        s[t] += v;
        __syncthreads();
    }
    boff[t] = (t == 0) ? 0 : s[t - 1];
    if (t == 255) rowp[n] = s[255];
}

__global__ void scan_final_kernel(int* __restrict__ degi,
                                  const int* __restrict__ boff,
                                  int* __restrict__ rowp,
                                  int* __restrict__ curs,
                                  float* __restrict__ dinv, int n) {
    __shared__ int s[SCAN_CHUNK];
    int t = threadIdx.x;
    int i = blockIdx.x * SCAN_CHUNK + t;
    int d = (i < n) ? degi[i] : 0;
    s[t] = d;
    __syncthreads();
    for (int off = 1; off < SCAN_CHUNK; off <<= 1) {
        int v = (t >= off) ? s[t - off] : 0;
        __syncthreads();
        s[t] += v;
        __syncthreads();
    }
    if (i < n) {
        int excl = s[t] - d + boff[blockIdx.x];
        rowp[i] = excl;
        curs[i] = excl;
        dinv[i] = 1.0f / fmaxf((float)d, 1.0f);
        degi[i] = 0;
    }
}

__global__ void scatter_kernel(const int* __restrict__ ei, int E, int nnodes,
                               int* __restrict__ curs, int* __restrict__ csr) {
    const int half2 = E >> 1;
    int i = blockIdx.x * blockDim.x + threadIdx.x;
    if (i < half2) {
        int2 s2 = __ldg(reinterpret_cast<const int2*>(ei) + i);
        int2 d2 = __ldg(reinterpret_cast<const int2*>(ei + E) + i);
        if ((unsigned)s2.x < (unsigned)nnodes && (unsigned)d2.x < (unsigned)nnodes) {
            int pos = atomicAdd(&curs[d2.x], 1);
            csr[pos] = s2.x;
        }
        if ((unsigned)s2.y < (unsigned)nnodes && (unsigned)d2.y < (unsigned)nnodes) {
            int pos = atomicAdd(&curs[d2.y], 1);
            csr[pos] = s2.y;
        }
    }
    if ((E & 1) && i == 0) {
        int s = __ldg(&ei[E - 1]);
        int d = __ldg(&ei[E + E - 1]);
        if ((unsigned)s < (unsigned)nnodes && (unsigned)d < (unsigned)nnodes) {
            int pos = atomicAdd(&curs[d], 1);
            csr[pos] = s;
        }
    }
}

// Gather-reduce mean aggregation, fp32 (layer 1).
template <int F4>
__global__ void gather_agg_kernel(const float4* __restrict__ in4,
                                  const int* __restrict__ rowp,
                                  const int* __restrict__ csr,
                                  const float* __restrict__ dinv,
                                  float4* __restrict__ aggout, int n) {
    constexpr int GPB = 256 / F4;
    const int node = blockIdx.x * GPB + (threadIdx.x / F4);
    const int lane = threadIdx.x & (F4 - 1);
    if (node >= n) return;

    const int beg = __ldg(&rowp[node]);
    const int end = __ldg(&rowp[node + 1]);

    float4 a0 = make_float4(0.f, 0.f, 0.f, 0.f);
    float4 a1 = make_float4(0.f, 0.f, 0.f, 0.f);
    float4 a2 = make_float4(0.f, 0.f, 0.f, 0.f);
    float4 a3 = make_float4(0.f, 0.f, 0.f, 0.f);

    int j = beg;
    for (; j + 4 <= end; j += 4) {
        int s0 = __ldg(&csr[j]);
        int s1 = __ldg(&csr[j + 1]);
        int s2 = __ldg(&csr[j + 2]);
        int s3 = __ldg(&csr[j + 3]);
        float4 v0 = __ldg(&in4[(size_t)s0 * F4 + lane]);
        float4 v1 = __ldg(&in4[(size_t)s1 * F4 + lane]);
        float4 v2 = __ldg(&in4[(size_t)s2 * F4 + lane]);
        float4 v3 = __ldg(&in4[(size_t)s3 * F4 + lane]);
        a0.x += v0.x; a0.y += v0.y; a0.z += v0.z; a0.w += v0.w;
        a1.x += v1.x; a1.y += v1.y; a1.z += v1.z; a1.w += v1.w;
        a2.x += v2.x; a2.y += v2.y; a2.z += v2.z; a2.w += v2.w;
        a3.x += v3.x; a3.y += v3.y; a3.z += v3.z; a3.w += v3.w;
    }
    for (; j < end; j++) {
        int s0 = __ldg(&csr[j]);
        float4 v0 = __ldg(&in4[(size_t)s0 * F4 + lane]);
        a0.x += v0.x; a0.y += v0.y; a0.z += v0.z; a0.w += v0.w;
    }

    const float di = __ldg(&dinv[node]);
    float4 r;
    r.x = (a0.x + a1.x + a2.x + a3.x) * di;
    r.y = (a0.y + a1.y + a2.y + a3.y) * di;
    r.z = (a0.z + a1.z + a2.z + a3.z) * di;
    r.w = (a0.w + a1.w + a2.w + a3.w) * di;
    aggout[(size_t)node * F4 + lane] = r;
}

// Gather-reduce mean aggregation over bf16x2-packed input (layer 2).
// 32 lanes/node; lane owns 4 features (uint2 = 4 bf16 = 8B per edge).
__global__ void gather_agg_bf16_kernel(const uint2* __restrict__ in16,
                                       const int* __restrict__ rowp,
                                       const int* __restrict__ csr,
                                       const float* __restrict__ dinv,
                                       float4* __restrict__ aggout, int n) {
    const int node = blockIdx.x * 8 + (threadIdx.x >> 5);
    const int lane = threadIdx.x & 31;
    if (node >= n) return;

    const int beg = __ldg(&rowp[node]);
    const int end = __ldg(&rowp[node + 1]);

    float4 a0 = make_float4(0.f, 0.f, 0.f, 0.f);
    float4 a1 = make_float4(0.f, 0.f, 0.f, 0.f);
    float4 a2 = make_float4(0.f, 0.f, 0.f, 0.f);
    float4 a3 = make_float4(0.f, 0.f, 0.f, 0.f);

    int j = beg;
    for (; j + 4 <= end; j += 4) {
        int s0 = __ldg(&csr[j]);
        int s1 = __ldg(&csr[j + 1]);
        int s2 = __ldg(&csr[j + 2]);
        int s3 = __ldg(&csr[j + 3]);
        uint2 w0 = __ldg(&in16[(size_t)s0 * 32 + lane]);
        uint2 w1 = __ldg(&in16[(size_t)s1 * 32 + lane]);
        uint2 w2 = __ldg(&in16[(size_t)s2 * 32 + lane]);
        uint2 w3 = __ldg(&in16[(size_t)s3 * 32 + lane]);
        float2 p;
        p = bunpack(w0.x); a0.x += p.x; a0.y += p.y;
        p = bunpack(w0.y); a0.z += p.x; a0.w += p.y;
        p = bunpack(w1.x); a1.x += p.x; a1.y += p.y;
        p = bunpack(w1.y); a1.z += p.x; a1.w += p.y;
        p = bunpack(w2.x); a2.x += p.x; a2.y += p.y;
        p = bunpack(w2.y); a2.z += p.x; a2.w += p.y;
        p = bunpack(w3.x); a3.x += p.x; a3.y += p.y;
        p = bunpack(w3.y); a3.z += p.x; a3.w += p.y;
    }
    for (; j < end; j++) {
        int s0 = __ldg(&csr[j]);
        uint2 w0 = __ldg(&in16[(size_t)s0 * 32 + lane]);
        float2 p;
        p = bunpack(w0.x); a0.x += p.x; a0.y += p.y;
        p = bunpack(w0.y); a0.z += p.x; a0.w += p.y;
    }

    const float di = __ldg(&dinv[node]);
    float4 r;
    r.x = (a0.x + a1.x + a2.x + a3.x) * di;
    r.y = (a0.y + a1.y + a2.y + a3.y) * di;
    r.z = (a0.z + a1.z + a2.z + a3.z) * di;
    r.w = (a0.w + a1.w + a2.w + a3.w) * di;
    aggout[(size_t)node * 32 + lane] = r;
}

// ---------------------------------------------------------------------------
// Pack weight fragments (unchanged).
__global__ void pack_bfrag_kernel(const float* __restrict__ W1l,
                                  const float* __restrict__ W1r,
                                  const float* __restrict__ W2l,
                                  const float* __restrict__ W2r,
                                  uint4* __restrict__ bf1,
                                  uint4* __restrict__ bf2) {
    int i = blockIdx.x * blockDim.x + threadIdx.x;
    int lane = i & 31, nt = (i >> 5) & 15, ks = i >> 9;
    int nrow = nt * 8 + (lane >> 2);
    int kb = (ks & 15) * 16 + (lane & 3) * 2;

    if (i < 8 * 16 * 32) {
        float v[4], hi[4], lo[4];
#pragma unroll
        for (int q = 0; q < 4; q++) {
            int k = kb + (q & 1) + (q >> 1) * 8;
            v[q] = (k < F_IN) ? W1l[nrow * F_IN + k]
                              : W1r[nrow * F_IN + (k - F_IN)];
            hi[q] = __bfloat162float(__float2bfloat16_rn(v[q]));
            lo[q] = v[q] - hi[q];
        }
        uint4 r;
        r.x = bpack(hi[0], hi[1]); r.y = bpack(hi[2], hi[3]);
        r.z = bpack(lo[0], lo[1]); r.w = bpack(lo[2], lo[3]);
        bf1[i] = r;
    }
    if (i < 16 * 16 * 32) {
        float v[4], hi[4], lo[4];
#pragma unroll
        for (int q = 0; q < 4; q++) {
            int k = kb + (q & 1) + (q >> 1) * 8;
            v[q] = (k < F_H) ? W2l[nrow * F_H + k]
                             : W2r[nrow * F_H + (k - F_H)];
            hi[q] = __bfloat162float(__float2bfloat16_rn(v[q]));
            lo[q] = v[q] - hi[q];
        }
        uint4 r;
        r.x = bpack(hi[0], hi[1]); r.y = bpack(hi[2], hi[3]);
        r.z = bpack(lo[0], lo[1]); r.w = bpack(lo[2], lo[3]);
        bf2[i] = r;
    }
}

// ---------------------------------------------------------------------------
// Dense layer via mma.sync bf16 split, double-buffered A staging.
// EMIT_BF16: also write bf16x2-packed output (for the next gather).
template <int K2, bool RELU, bool EMIT_BF16>
__global__ void __launch_bounds__(256, 2)
dense_mma_kernel(const float* __restrict__ xin,
                 const float* __restrict__ agg,
                 const uint4* __restrict__ bfrag,
                 const float* __restrict__ bias,
                 float* __restrict__ out,
                 uint32_t* __restrict__ out16, int n) {
    constexpr int NCH = K2 / 64;
    extern __shared__ char smem[];
    float* sBias = reinterpret_cast<float*>(smem + SMEM_BIAS_OFF);
    const uint32_t sA_u32 = smem_u32(smem);

    const int tid  = threadIdx.x;
    const int wid  = tid >> 5;
    const int lane = tid & 31;
    const int base = blockIdx.x * 128;

    if (tid < 128) sBias[tid] = bias[tid];

    float d[16][4];
#pragma unroll
    for (int nt = 0; nt < 16; nt++) {
        d[nt][0] = 0.f; d[nt][1] = 0.f; d[nt][2] = 0.f; d[nt][3] = 0.f;
    }

    auto stage = [&](int c) {
        char* buf = smem + (c & 1) * A_BUF;
        const float* src = (c < NCH / 2) ? (agg + c * 64)
                                         : (xin + (c - NCH / 2) * 64);
        const float2* s2 = reinterpret_cast<const float2*>(src);
#pragma unroll
        for (int ii = 0; ii < 16; ii++) {
            int i  = tid + ii * 256;
            int r  = i >> 5;
            int kp = i & 31;
            float2 v = make_float2(0.f, 0.f);
            int node = base + r;
            if (node < n) v = s2[(size_t)node * (K2 / 4) + kp];
            float hx = __bfloat162float(__float2bfloat16_rn(v.x));
            float hy = __bfloat162float(__float2bfloat16_rn(v.y));
            *reinterpret_cast<uint32_t*>(buf + r * A_STRIDE + kp * 4)
                = bpack(hx, hy);
            *reinterpret_cast<uint32_t*>(buf + A_TILE + r * A_STRIDE + kp * 4)
                = bpack(v.x - hx, v.y - hy);
        }
    };

    stage(0);
    __syncthreads();

#pragma unroll
    for (int c = 0; c < NCH; c++) {
        if (c + 1 < NCH) stage(c + 1);

        const uint32_t bufA = sA_u32 + (uint32_t)((c & 1) * A_BUF);
#pragma unroll
        for (int ks = 0; ks < 4; ks++) {
            const int gk = c * 4 + ks;
            uint32_t ah[4], al[4];
            {
                int row = lane & 15;
                int hf  = lane >> 4;
                uint32_t off = (uint32_t)((wid * 16 + row) * A_STRIDE
                                          + ks * 32 + hf * 16);
                LDMATRIX_X4(ah, bufA + off);
                LDMATRIX_X4(al, bufA + A_TILE + off);
            }
#pragma unroll
            for (int nt = 0; nt < 16; nt++) {
                uint4 bf = __ldg(&bfrag[(size_t)(gk * 16 + nt) * 32 + lane]);
                MMA_BF16(d[nt], ah, bf.x, bf.y);
                MMA_BF16(d[nt], ah, bf.z, bf.w);
                MMA_BF16(d[nt], al, bf.x, bf.y);
            }
        }
        __syncthreads();
    }

    // epilogue
    const int r0 = base + wid * 16 + (lane >> 2);
    const int r1 = r0 + 8;
    const int cb = (lane & 3) * 2;
    float2* o2 = reinterpret_cast<float2*>(out);
#pragma unroll
    for (int nt = 0; nt < 16; nt++) {
        int col = nt * 8 + cb;
        float bx = sBias[col], by = sBias[col + 1];
        if (r0 < n) {
            float2 o = make_float2(d[nt][0] + bx, d[nt][1] + by);
            if (RELU) { o.x = fmaxf(o.x, 0.f); o.y = fmaxf(o.y, 0.f); }
            o2[(size_t)r0 * 64 + (col >> 1)] = o;
            if (EMIT_BF16)
                out16[(size_t)r0 * 64 + (col >> 1)] = bpack(o.x, o.y);
        }
        if (r1 < n) {
            float2 o = make_float2(d[nt][2] + bx, d[nt][3] + by);
            if (RELU) { o.x = fmaxf(o.x, 0.f); o.y = fmaxf(o.y, 0.f); }
            o2[(size_t)r1 * 64 + (col >> 1)] = o;
            if (EMIT_BF16)
                out16[(size_t)r1 * 64 + (col >> 1)] = bpack(o.x, o.y);
        }
    }
}

// ---------------------------------------------------------------------------
extern "C" void kernel_launch(void* const* d_in, const int* in_sizes, int n_in,
                              void* d_out, int out_size) {
    const float* x    = (const float*)d_in[0];
    const int*   ei   = (const int*)d_in[1];
    const float* W1_l = (const float*)d_in[2];
    const float* b1   = (const float*)d_in[3];
    const float* W1_r = (const float*)d_in[4];
    const float* W2_l = (const float*)d_in[5];
    const float* b2   = (const float*)d_in[6];
    const float* W2_r = (const float*)d_in[7];
    float*       out  = (float*)d_out;

    const int n = in_sizes[0] / F_IN;   // 100000
    const int E = in_sizes[1] / 2;      // 1600000
    const int nblk = (n + SCAN_CHUNK - 1) / SCAN_CHUNK;

    void *p_agg1, *p_h, *p_h16, *p_agg2, *p_dinv, *p_degi, *p_rowp, *p_curs,
         *p_csr, *p_bsum, *p_boff, *p_bf1, *p_bf2;
    cudaGetSymbolAddress(&p_agg1, g_agg1);
    cudaGetSymbolAddress(&p_h,    g_h);
    cudaGetSymbolAddress(&p_h16,  g_h16);
    cudaGetSymbolAddress(&p_agg2, g_agg2);
    cudaGetSymbolAddress(&p_dinv, g_dinv);
    cudaGetSymbolAddress(&p_degi, g_degi);
    cudaGetSymbolAddress(&p_rowp, g_rowp);
    cudaGetSymbolAddress(&p_curs, g_curs);
    cudaGetSymbolAddress(&p_csr,  g_csr);
    cudaGetSymbolAddress(&p_bsum, g_bsum);
    cudaGetSymbolAddress(&p_boff, g_boff);
    cudaGetSymbolAddress(&p_bf1,  g_bf1);
    cudaGetSymbolAddress(&p_bf2,  g_bf2);
    float*    agg1 = (float*)p_agg1;
    float*    h    = (float*)p_h;
    uint32_t* h16  = (uint32_t*)p_h16;
    float*    agg2 = (float*)p_agg2;
    float*    dinv = (float*)p_dinv;
    int*      degi = (int*)p_degi;
    int*      rowp = (int*)p_rowp;
    int*      curs = (int*)p_curs;
    int*      csr  = (int*)p_csr;
    int*      bsum = (int*)p_bsum;
    int*      boff = (int*)p_boff;
    uint4*    bf1  = (uint4*)p_bf1;
    uint4*    bf2  = (uint4*)p_bf2;

    cudaFuncSetAttribute(dense_mma_kernel<128, true, true>,
                         cudaFuncAttributeMaxDynamicSharedMemorySize, SMEM_TOTAL_D);
    cudaFuncSetAttribute(dense_mma_kernel<256, false, false>,
                         cudaFuncAttributeMaxDynamicSharedMemorySize, SMEM_TOTAL_D);

    // CSR build
    hist_kernel<<<((E >> 1) + 255) / 256, 256>>>(ei, E, n, degi);
    scan_partial_kernel<<<nblk, SCAN_CHUNK>>>(degi, bsum, n);
    scan_bsum_kernel<<<1, 256>>>(bsum, boff, rowp, nblk, n);
    scan_final_kernel<<<nblk, SCAN_CHUNK>>>(degi, boff, rowp, curs, dinv, n);
    scatter_kernel<<<((E >> 1) + 255) / 256, 256>>>(ei, E, n, curs, csr);

    // weight fragments
    pack_bfrag_kernel<<<(16 * 16 * 32 + 255) / 256, 256>>>(
        W1_l, W1_r, W2_l, W2_r, bf1, bf2);

    const int dblk = (n + 127) / 128;

    // layer 1
    gather_agg_kernel<F_IN / 4><<<(n * (F_IN / 4) + 255) / 256, 256>>>(
        (const float4*)x, rowp, csr, dinv, (float4*)agg1, n);
    dense_mma_kernel<128, true, true><<<dblk, 256, SMEM_TOTAL_D>>>(
        x, agg1, bf1, b1, h, h16, n);

    // layer 2 (aggregation over bf16 h)
    gather_agg_bf16_kernel<<<(n + 7) / 8, 256>>>(
        (const uint2*)h16, rowp, csr, dinv, (float4*)agg2, n);
    dense_mma_kernel<256, false, false><<<dblk, 256, SMEM_TOTAL_D>>>(
        h, agg2, bf2, b2, out, nullptr, n);
}

// round 16
// speedup vs baseline: 1.0349x; 1.0349x over previous
#include <cuda_runtime.h>
#include <cuda_bf16.h>
#include <cstdint>

// ---------------------------------------------------------------------------
// GraphSAGE 2-layer backbone.
// R16 = R14 (best: 286us) + software-pipelined CSR index prefetch in gathers:
//       next 4 indices load while current 4 feature-rows load (breaks the
//       idx->data latency chain that bound the gather kernels).
// Dense: mma.sync bf16 hi/lo split, double-buffered A staging (unchanged).
// ---------------------------------------------------------------------------

static constexpr int NN   = 100000;
static constexpr int EE   = 1600000;
static constexpr int F_IN = 64;
static constexpr int F_H  = 128;
static constexpr int SCAN_CHUNK = 512;

static constexpr int A_STRIDE = 144;
static constexpr int A_TILE   = 128 * A_STRIDE;
static constexpr int A_BUF    = 2 * A_TILE;
static constexpr int SMEM_BIAS_OFF = 2 * A_BUF;             // 73728
static constexpr int SMEM_TOTAL_D  = SMEM_BIAS_OFF + 512;   // 74240

// scratch
__device__ __align__(16) float g_agg1 [(size_t)NN * F_IN];
__device__ __align__(16) float g_h    [(size_t)NN * F_H];
__device__ __align__(16) float g_agg2 [(size_t)NN * F_H];
__device__ __align__(16) float g_dinv [NN];
__device__ __align__(16) int   g_degi [NN];
__device__ __align__(16) int   g_rowp [NN + 1];
__device__ __align__(16) int   g_curs [NN];
__device__ __align__(16) int   g_csr  [EE];
__device__ __align__(16) int   g_bsum [256];
__device__ __align__(16) int   g_boff [256];
__device__ __align__(16) uint4 g_bf1 [8  * 16 * 32];
__device__ __align__(16) uint4 g_bf2 [16 * 16 * 32];

// ---------------------------------------------------------------------------
__device__ __forceinline__ uint32_t smem_u32(const void* p) {
    uint32_t a;
    asm("{ .reg .u64 t; cvta.to.shared.u64 t, %1; cvt.u32.u64 %0, t; }"
        : "=r"(a) : "l"(p));
    return a;
}
__device__ __forceinline__ uint32_t bpack(float a, float b) {
    __nv_bfloat16 ha = __float2bfloat16_rn(a), hb = __float2bfloat16_rn(b);
    return (uint32_t)__bfloat16_as_ushort(ha)
         | ((uint32_t)__bfloat16_as_ushort(hb) << 16);
}

#define MMA_BF16(d, a, b0, b1)                                              \
    asm volatile("mma.sync.aligned.m16n8k16.row.col.f32.bf16.bf16.f32 "     \
        "{%0,%1,%2,%3}, {%4,%5,%6,%7}, {%8,%9}, {%0,%1,%2,%3};"             \
        : "+f"((d)[0]), "+f"((d)[1]), "+f"((d)[2]), "+f"((d)[3])            \
        : "r"((a)[0]), "r"((a)[1]), "r"((a)[2]), "r"((a)[3]),               \
          "r"(b0), "r"(b1))

#define LDMATRIX_X4(r, addr)                                                \
    asm volatile("ldmatrix.sync.aligned.m8n8.x4.shared.b16 "                \
        "{%0,%1,%2,%3}, [%4];"                                              \
        : "=r"((r)[0]), "=r"((r)[1]), "=r"((r)[2]), "=r"((r)[3])            \
        : "r"(addr))

// ---------------------------------------------------------------------------
// CSR build (unchanged)
__global__ void hist_kernel(const int* __restrict__ ei, int E, int nnodes,
                            int* __restrict__ degi) {
    const int half2 = E >> 1;
    int i = blockIdx.x * blockDim.x + threadIdx.x;
    if (i < half2) {
        int2 d2 = __ldg(reinterpret_cast<const int2*>(ei + E) + i);
        if ((unsigned)d2.x < (unsigned)nnodes) atomicAdd(&degi[d2.x], 1);
        if ((unsigned)d2.y < (unsigned)nnodes) atomicAdd(&degi[d2.y], 1);
    }
    if ((E & 1) && i == 0) {
        int d = __ldg(&ei[E + E - 1]);
        if ((unsigned)d < (unsigned)nnodes) atomicAdd(&degi[d], 1);
    }
}

__global__ void scan_partial_kernel(const int* __restrict__ degi,
                                    int* __restrict__ bsum, int n) {
    __shared__ int s[SCAN_CHUNK];
    int t = threadIdx.x;
    int i = blockIdx.x * SCAN_CHUNK + t;
    s[t] = (i < n) ? degi[i] : 0;
    __syncthreads();
    for (int off = SCAN_CHUNK / 2; off > 0; off >>= 1) {
        if (t < off) s[t] += s[t + off];
        __syncthreads();
    }
    if (t == 0) bsum[blockIdx.x] = s[0];
}

__global__ void scan_bsum_kernel(const int* __restrict__ bsum,
                                 int* __restrict__ boff,
                                 int* __restrict__ rowp, int nblk, int n) {
    __shared__ int s[256];
    int t = threadIdx.x;
    s[t] = (t < nblk) ? bsum[t] : 0;
    __syncthreads();
    for (int off = 1; off < 256; off <<= 1) {
        int v = (t >= off) ? s[t - off] : 0;
        __syncthreads();
        s[t] += v;
        __syncthreads();
    }
    boff[t] = (t == 0) ? 0 : s[t - 1];
    if (t == 255) rowp[n] = s[255];
}

__global__ void scan_final_kernel(int* __restrict__ degi,
                                  const int* __restrict__ boff,
                                  int* __restrict__ rowp,
                                  int* __restrict__ curs,
                                  float* __restrict__ dinv, int n) {
    __shared__ int s[SCAN_CHUNK];
    int t = threadIdx.x;
    int i = blockIdx.x * SCAN_CHUNK + t;
    int d = (i < n) ? degi[i] : 0;
    s[t] = d;
    __syncthreads();
    for (int off = 1; off < SCAN_CHUNK; off <<= 1) {
        int v = (t >= off) ? s[t - off] : 0;
        __syncthreads();
        s[t] += v;
        __syncthreads();
    }
    if (i < n) {
        int excl = s[t] - d + boff[blockIdx.x];
        rowp[i] = excl;
        curs[i] = excl;
        dinv[i] = 1.0f / fmaxf((float)d, 1.0f);
        degi[i] = 0;
    }
}

__global__ void scatter_kernel(const int* __restrict__ ei, int E, int nnodes,
                               int* __restrict__ curs, int* __restrict__ csr) {
    const int half2 = E >> 1;
    int i = blockIdx.x * blockDim.x + threadIdx.x;
    if (i < half2) {
        int2 s2 = __ldg(reinterpret_cast<const int2*>(ei) + i);
        int2 d2 = __ldg(reinterpret_cast<const int2*>(ei + E) + i);
        if ((unsigned)s2.x < (unsigned)nnodes && (unsigned)d2.x < (unsigned)nnodes) {
            int pos = atomicAdd(&curs[d2.x], 1);
            csr[pos] = s2.x;
        }
        if ((unsigned)s2.y < (unsigned)nnodes && (unsigned)d2.y < (unsigned)nnodes) {
            int pos = atomicAdd(&curs[d2.y], 1);
            csr[pos] = s2.y;
        }
    }
    if ((E & 1) && i == 0) {
        int s = __ldg(&ei[E - 1]);
        int d = __ldg(&ei[E + E - 1]);
        if ((unsigned)s < (unsigned)nnodes && (unsigned)d < (unsigned)nnodes) {
            int pos = atomicAdd(&curs[d], 1);
            csr[pos] = s;
        }
    }
}

// ---------------------------------------------------------------------------
// Gather-reduce mean aggregation, software-pipelined index prefetch.
// Indices for batch i+1 load while feature rows for batch i load.
template <int F4>
__global__ void gather_agg_kernel(const float4* __restrict__ in4,
                                  const int* __restrict__ rowp,
                                  const int* __restrict__ csr,
                                  const float* __restrict__ dinv,
                                  float4* __restrict__ aggout, int n) {
    constexpr int GPB = 256 / F4;
    const int node = blockIdx.x * GPB + (threadIdx.x / F4);
    const int lane = threadIdx.x & (F4 - 1);
    if (node >= n) return;

    const int   beg = __ldg(&rowp[node]);
    const int   end = __ldg(&rowp[node + 1]);
    const float di  = __ldg(&dinv[node]);

    float4 a0 = make_float4(0.f, 0.f, 0.f, 0.f);
    float4 a1 = make_float4(0.f, 0.f, 0.f, 0.f);
    float4 a2 = make_float4(0.f, 0.f, 0.f, 0.f);
    float4 a3 = make_float4(0.f, 0.f, 0.f, 0.f);

    int j = beg;
    int ni0 = 0, ni1 = 0, ni2 = 0, ni3 = 0;
    if (j + 4 <= end) {                       // prologue: first index batch
        ni0 = __ldg(&csr[j]);
        ni1 = __ldg(&csr[j + 1]);
        ni2 = __ldg(&csr[j + 2]);
        ni3 = __ldg(&csr[j + 3]);
    }
    for (; j + 8 <= end; j += 4) {
        const int c0 = ni0, c1 = ni1, c2 = ni2, c3 = ni3;
        ni0 = __ldg(&csr[j + 4]);             // prefetch next batch
        ni1 = __ldg(&csr[j + 5]);
        ni2 = __ldg(&csr[j + 6]);
        ni3 = __ldg(&csr[j + 7]);
        float4 v0 = __ldg(&in4[(size_t)c0 * F4 + lane]);
        float4 v1 = __ldg(&in4[(size_t)c1 * F4 + lane]);
        float4 v2 = __ldg(&in4[(size_t)c2 * F4 + lane]);
        float4 v3 = __ldg(&in4[(size_t)c3 * F4 + lane]);
        a0.x += v0.x; a0.y += v0.y; a0.z += v0.z; a0.w += v0.w;
        a1.x += v1.x; a1.y += v1.y; a1.z += v1.z; a1.w += v1.w;
        a2.x += v2.x; a2.y += v2.y; a2.z += v2.z; a2.w += v2.w;
        a3.x += v3.x; a3.y += v3.y; a3.z += v3.z; a3.w += v3.w;
    }
    if (j + 4 <= end) {                       // last full batch (indices ready)
        float4 v0 = __ldg(&in4[(size_t)ni0 * F4 + lane]);
        float4 v1 = __ldg(&in4[(size_t)ni1 * F4 + lane]);
        float4 v2 = __ldg(&in4[(size_t)ni2 * F4 + lane]);
        float4 v3 = __ldg(&in4[(size_t)ni3 * F4 + lane]);
        a0.x += v0.x; a0.y += v0.y; a0.z += v0.z; a0.w += v0.w;
        a1.x += v1.x; a1.y += v1.y; a1.z += v1.z; a1.w += v1.w;
        a2.x += v2.x; a2.y += v2.y; a2.z += v2.z; a2.w += v2.w;
        a3.x += v3.x; a3.y += v3.y; a3.z += v3.z; a3.w += v3.w;
        j += 4;
    }
    for (; j < end; j++) {                    // tail
        int s0 = __ldg(&csr[j]);
        float4 v0 = __ldg(&in4[(size_t)s0 * F4 + lane]);
        a0.x += v0.x; a0.y += v0.y; a0.z += v0.z; a0.w += v0.w;
    }

    float4 r;
    r.x = (a0.x + a1.x + a2.x + a3.x) * di;
    r.y = (a0.y + a1.y + a2.y + a3.y) * di;
    r.z = (a0.z + a1.z + a2.z + a3.z) * di;
    r.w = (a0.w + a1.w + a2.w + a3.w) * di;
    aggout[(size_t)node * F4 + lane] = r;
}

// ---------------------------------------------------------------------------
// Pack weight fragments (unchanged).
__global__ void pack_bfrag_kernel(const float* __restrict__ W1l,
                                  const float* __restrict__ W1r,
                                  const float* __restrict__ W2l,
                                  const float* __restrict__ W2r,
                                  uint4* __restrict__ bf1,
                                  uint4* __restrict__ bf2) {
    int i = blockIdx.x * blockDim.x + threadIdx.x;
    int lane = i & 31, nt = (i >> 5) & 15, ks = i >> 9;
    int nrow = nt * 8 + (lane >> 2);
    int kb = (ks & 15) * 16 + (lane & 3) * 2;

    if (i < 8 * 16 * 32) {
        float v[4], hi[4], lo[4];
#pragma unroll
        for (int q = 0; q < 4; q++) {
            int k = kb + (q & 1) + (q >> 1) * 8;
            v[q] = (k < F_IN) ? W1l[nrow * F_IN + k]
                              : W1r[nrow * F_IN + (k - F_IN)];
            hi[q] = __bfloat162float(__float2bfloat16_rn(v[q]));
            lo[q] = v[q] - hi[q];
        }
        uint4 r;
        r.x = bpack(hi[0], hi[1]); r.y = bpack(hi[2], hi[3]);
        r.z = bpack(lo[0], lo[1]); r.w = bpack(lo[2], lo[3]);
        bf1[i] = r;
    }
    if (i < 16 * 16 * 32) {
        float v[4], hi[4], lo[4];
#pragma unroll
        for (int q = 0; q < 4; q++) {
            int k = kb + (q & 1) + (q >> 1) * 8;
            v[q] = (k < F_H) ? W2l[nrow * F_H + k]
                             : W2r[nrow * F_H + (k - F_H)];
            hi[q] = __bfloat162float(__float2bfloat16_rn(v[q]));
            lo[q] = v[q] - hi[q];
        }
        uint4 r;
        r.x = bpack(hi[0], hi[1]); r.y = bpack(hi[2], hi[3]);
        r.z = bpack(lo[0], lo[1]); r.w = bpack(lo[2], lo[3]);
        bf2[i] = r;
    }
}

// ---------------------------------------------------------------------------
// Dense layer via mma.sync bf16 split, double-buffered A staging (R14).
template <int K2, bool RELU>
__global__ void __launch_bounds__(256, 2)
dense_mma_kernel(const float* __restrict__ xin,
                 const float* __restrict__ agg,
                 const uint4* __restrict__ bfrag,
                 const float* __restrict__ bias,
                 float* __restrict__ out, int n) {
    constexpr int NCH = K2 / 64;
    extern __shared__ char smem[];
    float* sBias = reinterpret_cast<float*>(smem + SMEM_BIAS_OFF);
    const uint32_t sA_u32 = smem_u32(smem);

    const int tid  = threadIdx.x;
    const int wid  = tid >> 5;
    const int lane = tid & 31;
    const int base = blockIdx.x * 128;

    if (tid < 128) sBias[tid] = bias[tid];

    float d[16][4];
#pragma unroll
    for (int nt = 0; nt < 16; nt++) {
        d[nt][0] = 0.f; d[nt][1] = 0.f; d[nt][2] = 0.f; d[nt][3] = 0.f;
    }

    auto stage = [&](int c) {
        char* buf = smem + (c & 1) * A_BUF;
        const float* src = (c < NCH / 2) ? (agg + c * 64)
                                         : (xin + (c - NCH / 2) * 64);
        const float2* s2 = reinterpret_cast<const float2*>(src);
#pragma unroll
        for (int ii = 0; ii < 16; ii++) {
            int i  = tid + ii * 256;
            int r  = i >> 5;
            int kp = i & 31;
            float2 v = make_float2(0.f, 0.f);
            int node = base + r;
            if (node < n) v = s2[(size_t)node * (K2 / 4) + kp];
            float hx = __bfloat162float(__float2bfloat16_rn(v.x));
            float hy = __bfloat162float(__float2bfloat16_rn(v.y));
            *reinterpret_cast<uint32_t*>(buf + r * A_STRIDE + kp * 4)
                = bpack(hx, hy);
            *reinterpret_cast<uint32_t*>(buf + A_TILE + r * A_STRIDE + kp * 4)
                = bpack(v.x - hx, v.y - hy);
        }
    };

    stage(0);
    __syncthreads();

#pragma unroll
    for (int c = 0; c < NCH; c++) {
        if (c + 1 < NCH) stage(c + 1);

        const uint32_t bufA = sA_u32 + (uint32_t)((c & 1) * A_BUF);
#pragma unroll
        for (int ks = 0; ks < 4; ks++) {
            const int gk = c * 4 + ks;
            uint32_t ah[4], al[4];
            {
                int row = lane & 15;
                int hf  = lane >> 4;
                uint32_t off = (uint32_t)((wid * 16 + row) * A_STRIDE
                                          + ks * 32 + hf * 16);
                LDMATRIX_X4(ah, bufA + off);
                LDMATRIX_X4(al, bufA + A_TILE + off);
            }
#pragma unroll
            for (int nt = 0; nt < 16; nt++) {
                uint4 bf = __ldg(&bfrag[(size_t)(gk * 16 + nt) * 32 + lane]);
                MMA_BF16(d[nt], ah, bf.x, bf.y);   // hi * hi
                MMA_BF16(d[nt], ah, bf.z, bf.w);   // hi * lo
                MMA_BF16(d[nt], al, bf.x, bf.y);   // lo * hi
            }
        }
        __syncthreads();
    }

    // epilogue: bias + relu, float2 stores
    const int r0 = base + wid * 16 + (lane >> 2);
    const int r1 = r0 + 8;
    const int cb = (lane & 3) * 2;
    float2* o2 = reinterpret_cast<float2*>(out);
#pragma unroll
    for (int nt = 0; nt < 16; nt++) {
        int col = nt * 8 + cb;
        float bx = sBias[col], by = sBias[col + 1];
        if (r0 < n) {
            float2 o = make_float2(d[nt][0] + bx, d[nt][1] + by);
            if (RELU) { o.x = fmaxf(o.x, 0.f); o.y = fmaxf(o.y, 0.f); }
            o2[(size_t)r0 * 64 + (col >> 1)] = o;
        }
        if (r1 < n) {
            float2 o = make_float2(d[nt][2] + bx, d[nt][3] + by);
            if (RELU) { o.x = fmaxf(o.x, 0.f); o.y = fmaxf(o.y, 0.f); }
            o2[(size_t)r1 * 64 + (col >> 1)] = o;
        }
    }
}

// ---------------------------------------------------------------------------
extern "C" void kernel_launch(void* const* d_in, const int* in_sizes, int n_in,
                              void* d_out, int out_size) {
    const float* x    = (const float*)d_in[0];
    const int*   ei   = (const int*)d_in[1];
    const float* W1_l = (const float*)d_in[2];
    const float* b1   = (const float*)d_in[3];
    const float* W1_r = (const float*)d_in[4];
    const float* W2_l = (const float*)d_in[5];
    const float* b2   = (const float*)d_in[6];
    const float* W2_r = (const float*)d_in[7];
    float*       out  = (float*)d_out;

    const int n = in_sizes[0] / F_IN;   // 100000
    const int E = in_sizes[1] / 2;      // 1600000
    const int nblk = (n + SCAN_CHUNK - 1) / SCAN_CHUNK;

    void *p_agg1, *p_h, *p_agg2, *p_dinv, *p_degi, *p_rowp, *p_curs, *p_csr,
         *p_bsum, *p_boff, *p_bf1, *p_bf2;
    cudaGetSymbolAddress(&p_agg1, g_agg1);
    cudaGetSymbolAddress(&p_h,    g_h);
    cudaGetSymbolAddress(&p_agg2, g_agg2);
    cudaGetSymbolAddress(&p_dinv, g_dinv);
    cudaGetSymbolAddress(&p_degi, g_degi);
    cudaGetSymbolAddress(&p_rowp, g_rowp);
    cudaGetSymbolAddress(&p_curs, g_curs);
    cudaGetSymbolAddress(&p_csr,  g_csr);
    cudaGetSymbolAddress(&p_bsum, g_bsum);
    cudaGetSymbolAddress(&p_boff, g_boff);
    cudaGetSymbolAddress(&p_bf1,  g_bf1);
    cudaGetSymbolAddress(&p_bf2,  g_bf2);
    float* agg1 = (float*)p_agg1;
    float* h    = (float*)p_h;
    float* agg2 = (float*)p_agg2;
    float* dinv = (float*)p_dinv;
    int*   degi = (int*)p_degi;
    int*   rowp = (int*)p_rowp;
    int*   curs = (int*)p_curs;
    int*   csr  = (int*)p_csr;
    int*   bsum = (int*)p_bsum;
    int*   boff = (int*)p_boff;
    uint4* bf1  = (uint4*)p_bf1;
    uint4* bf2  = (uint4*)p_bf2;

    cudaFuncSetAttribute(dense_mma_kernel<128, true>,
                         cudaFuncAttributeMaxDynamicSharedMemorySize, SMEM_TOTAL_D);
    cudaFuncSetAttribute(dense_mma_kernel<256, false>,
                         cudaFuncAttributeMaxDynamicSharedMemorySize, SMEM_TOTAL_D);

    // CSR build
    hist_kernel<<<((E >> 1) + 255) / 256, 256>>>(ei, E, n, degi);
    scan_partial_kernel<<<nblk, SCAN_CHUNK>>>(degi, bsum, n);
    scan_bsum_kernel<<<1, 256>>>(bsum, boff, rowp, nblk, n);
    scan_final_kernel<<<nblk, SCAN_CHUNK>>>(degi, boff, rowp, curs, dinv, n);
    scatter_kernel<<<((E >> 1) + 255) / 256, 256>>>(ei, E, n, curs, csr);

    // weight fragments
    pack_bfrag_kernel<<<(16 * 16 * 32 + 255) / 256, 256>>>(
        W1_l, W1_r, W2_l, W2_r, bf1, bf2);

    const int dblk = (n + 127) / 128;

    // layer 1
    gather_agg_kernel<F_IN / 4><<<(n * (F_IN / 4) + 255) / 256, 256>>>(
        (const float4*)x, rowp, csr, dinv, (float4*)agg1, n);
    dense_mma_kernel<128, true><<<dblk, 256, SMEM_TOTAL_D>>>(
        x, agg1, bf1, b1, h, n);

    // layer 2
    gather_agg_kernel<F_H / 4><<<(n * (F_H / 4) + 255) / 256, 256>>>(
        (const float4*)h, rowp, csr, dinv, (float4*)agg2, n);
    dense_mma_kernel<256, false><<<dblk, 256, SMEM_TOTAL_D>>>(
        h, agg2, bf2, b2, out, n);
}